// round 7
// baseline (speedup 1.0000x reference)
#include <cuda_runtime.h>

#define BB 256
#define TT 500
#define NC 100
#define NA 13

// scratch: x = FM @ lr_w^T + lr_b  [B,T,2]
__device__ float g_x[BB * TT * 2];
// scratch: per-(b,t,a) probability of the observed outcome
__device__ float g_G[BB * TT * NA];
// scratch: per-(b,t,a) chunk-local (prefix + lg_o) pairs
__device__ float2 g_v[BB * TT * NA];

// ---------------------------------------------------------------------------
// Kernel 1: x[b,t,o] = sum_f FM[b,t,f] * lr_w[o,f] + lr_b[o]
// ---------------------------------------------------------------------------
__global__ void __launch_bounds__(256) x_kernel(const float* __restrict__ FM,
                                                const float* __restrict__ lr_w,
                                                const float* __restrict__ lr_b) {
    __shared__ float4 w0[50], w1[50];
    int tid = threadIdx.x;
    if (tid < 50) {
        w0[tid] = ((const float4*)lr_w)[tid];
        w1[tid] = ((const float4*)lr_w)[50 + tid];
    }
    __syncthreads();
    int lane = tid & 31;
    int wrow = (blockIdx.x * 8 + (tid >> 5)) * 2;
    if (wrow >= BB * TT) return;
    const float4* fa = (const float4*)(FM + (size_t)wrow * 200);
    const float4* fb = fa + 50;

    float4 va0 = __ldg(fa + lane);
    float4 vb0 = __ldg(fb + lane);
    float4 va1, vb1;
    bool tail = lane < 18;
    if (tail) {
        va1 = __ldg(fa + 32 + lane);
        vb1 = __ldg(fb + 32 + lane);
    }
    float4 u = w0[lane], s = w1[lane];
    float a0 = va0.x * u.x + va0.y * u.y + va0.z * u.z + va0.w * u.w;
    float a1 = va0.x * s.x + va0.y * s.y + va0.z * s.z + va0.w * s.w;
    float b0 = vb0.x * u.x + vb0.y * u.y + vb0.z * u.z + vb0.w * u.w;
    float b1 = vb0.x * s.x + vb0.y * s.y + vb0.z * s.z + vb0.w * s.w;
    if (tail) {
        float4 u2 = w0[32 + lane], s2 = w1[32 + lane];
        a0 += va1.x * u2.x + va1.y * u2.y + va1.z * u2.z + va1.w * u2.w;
        a1 += va1.x * s2.x + va1.y * s2.y + va1.z * s2.z + va1.w * s2.w;
        b0 += vb1.x * u2.x + vb1.y * u2.y + vb1.z * u2.z + vb1.w * u2.w;
        b1 += vb1.x * s2.x + vb1.y * s2.y + vb1.z * s2.z + vb1.w * s2.w;
    }
#pragma unroll
    for (int off = 16; off; off >>= 1) {
        a0 += __shfl_xor_sync(0xffffffffu, a0, off);
        a1 += __shfl_xor_sync(0xffffffffu, a1, off);
        b0 += __shfl_xor_sync(0xffffffffu, b0, off);
        b1 += __shfl_xor_sync(0xffffffffu, b1, off);
    }
    if (lane == 0) {
        float bb0 = __ldg(lr_b), bb1 = __ldg(lr_b + 1);
        ((float4*)g_x)[wrow >> 1] = make_float4(a0 + bb0, a1 + bb1, b0 + bb0, b1 + bb1);
    }
}

// ---------------------------------------------------------------------------
// Kernel 2: sequential scan, linear-space normalized alpha, minimal core.
// Streams Gy = P(observed outcome) to g_G; all logs deferred to post_kernel.
// alpha layout [c][a][s] -> one LDS.64 / STS.64 per step.
// ---------------------------------------------------------------------------
__global__ void __launch_bounds__(32) scan_kernel(
    const int* __restrict__ corr, const int* __restrict__ kc,
    const int* __restrict__ prob, const float* __restrict__ trans_logits,
    const float* __restrict__ olp, const float* __restrict__ olk,
    const float* __restrict__ init_logits) {
    __shared__ float  s_la[NC * NA * 2];  // alpha [c][a][s], sum_s = 1
    __shared__ float4 s_T[TT + 1];        // trans probs (T00,T01,T10,T11)
    __shared__ float4 s_D[TT + 1];        // (Dy0, Dy1, sy, pad)
    __shared__ int    s_kc[TT + 1];

    const int b = blockIdx.x;
    const int lane = threadIdx.x;
    const int laneA = (lane < NA) ? lane : 0;

    const float4* olp4 = (const float4*)olp;
    const float4* olk4 = (const float4*)olk;
    const float4* tl4  = (const float4*)trans_logits;
    const float2* gx2  = (const float2*)g_x;

    // ---- stage per-step tables ----
    for (int i = lane; i < TT; i += 32) {
        int c = kc[b * TT + i];
        int p = prob[b * TT + i];
        int y = corr[b * TT + i];
        s_kc[i] = c;
        float4 op = __ldg(olp4 + p);
        float4 ok = __ldg(olk4 + c);
        float2 xv = gx2[b * TT + i];
        float sy = y ? 1.f : -1.f;
        float D0 = (op.y - op.x) + (ok.y - ok.x) - 2.f * xv.x;
        float D1 = (op.w - op.z) + (ok.w - ok.z) - 2.f * xv.y;
        s_D[i] = make_float4(sy * D0, sy * D1, sy, 0.f);
        float4 t = __ldg(tl4 + c);  // [snew0,sold0],[0,1],[1,0],[1,1]
        float m0 = fmaxf(t.x, t.z), m1 = fmaxf(t.y, t.w);
        float e00 = __expf(t.x - m0), e10 = __expf(t.z - m0);
        float e01 = __expf(t.y - m1), e11 = __expf(t.w - m1);
        float r0 = __fdividef(1.f, e00 + e10);
        float r1 = __fdividef(1.f, e01 + e11);
        s_T[i] = make_float4(e00 * r0, e01 * r1, e10 * r0, e11 * r1);
    }
    if (lane == 0) {
        s_kc[TT] = 0;
        s_D[TT] = make_float4(0.f, 0.f, 1.f, 0.f);
        s_T[TT] = make_float4(0.5f, 0.5f, 0.5f, 0.5f);
    }
    // ---- init alpha (linear, normalized) ----
    for (int i = lane; i < NC; i += 32) {
        float2 il = ((const float2*)init_logits)[i];
        float m = fmaxf(il.x, il.y);
        float ex = __expf(il.x - m), ey = __expf(il.y - m);
        float r = __fdividef(1.f, ex + ey);
        float A0i = ex * r, A1i = ey * r;
#pragma unroll
        for (int a2 = 0; a2 < NA; ++a2) {
            s_la[i * (2 * NA) + 2 * a2]     = A0i;
            s_la[i * (2 * NA) + 2 * a2 + 1] = A1i;
        }
    }
    __syncwarp();

    const bool act = lane < NA;
    const float ab2 = 2.f * (-3.0f + 0.5f * (float)laneA);  // 2*ab[a]
    float* gG = g_G + (size_t)b * TT * NA + lane;

    int c = s_kc[0];
    float4 D = s_D[0];
    float4 T = s_T[0];
    float2 Ain = *(const float2*)&s_la[c * (2 * NA) + 2 * laneA];
    float A0 = Ain.x, A1 = Ain.y;

#pragma unroll 4
    for (int t = 0; t < TT; ++t) {
        // prefetch t+1 (alpha read BEFORE this step's store; same-chain forwarded)
        int    c1 = s_kc[t + 1];
        float4 Dn = s_D[t + 1];
        float4 Tn = s_T[t + 1];
        float2 An = *(const float2*)&s_la[c1 * (2 * NA) + 2 * laneA];

        // p(s, observed y) = sigmoid(sy*(D_s + ab2))
        float z0 = fmaf(D.z, ab2, D.x);
        float z1 = fmaf(D.z, ab2, D.y);
        float p0 = __fdividef(1.f, 1.f + __expf(-z0));
        float p1 = __fdividef(1.f, 1.f + __expf(-z1));

        float u0 = p0 * A0, u1 = p1 * A1;
        float Gy = u0 + u1;                 // prob of observed outcome
        if (act) gG[t * NA] = Gy;           // fire-and-forget

        float nA0 = fmaf(u0, T.x, u1 * T.y);
        float nA1 = fmaf(u0, T.z, u1 * T.w);
        float rcp = __fdividef(1.f, Gy);    // nA0+nA1 == Gy -> renormalize
        float A0p = nA0 * rcp;
        float A1p = nA1 * rcp;
        if (act) *(float2*)&s_la[c * (2 * NA) + 2 * lane] = make_float2(A0p, A1p);

        bool same = (c1 == c);
        A0 = same ? A0p : An.x;
        A1 = same ? A1p : An.y;
        c = c1; D = Dn; T = Tn;
    }
}

// ---------------------------------------------------------------------------
// Kernel 3: per-batch postprocess. Block per b (256 threads, 8 warps).
// Phase 1: 8-way chunked prefix of log(Gy): warp w handles t in [w*63,(w+1)*63),
//          lanes 0-12 = ability levels; writes chunk-local (pre+lg0, pre+lg1)
//          to g_v and chunk sums to smem.
// Phase 2: carry table from chunk sums; each warp reduces rows t=wid+8k over a,
//          adding the carry, and writes the normalized output.
// ---------------------------------------------------------------------------
#define CH 63
__global__ void __launch_bounds__(256) post_kernel(const int* __restrict__ corr,
                                                   float* __restrict__ out) {
    __shared__ int   s_y[TT];
    __shared__ float s_csum[8][NA];
    __shared__ float s_carry[8][NA];

    const int b = blockIdx.x;
    const int tid = threadIdx.x;
    const int wid = tid >> 5;
    const int lane = tid & 31;
    const int laneA = (lane < NA) ? lane : 0;

    for (int i = tid; i < TT; i += 256) s_y[i] = corr[b * TT + i];
    __syncthreads();

    const float* gG = g_G + (size_t)b * TT * NA + laneA;
    float2* gv = g_v + (size_t)b * TT * NA + laneA;

    // ---- phase 1: chunk-local prefix ----
    {
        int t0 = wid * CH;
        int t1 = min(t0 + CH, TT);
        float acc = 0.f;
        for (int t = t0; t < t1; ++t) {
            float Gy = gG[t * NA];
            int y = s_y[t];
            float lgy = __logf(Gy);
            float lgo = __logf(fmaxf(1.f - Gy, 1e-37f));
            float v0 = y ? lgo : lgy;
            float v1 = y ? lgy : lgo;
            if (lane < NA) gv[t * NA] = make_float2(acc + v0, acc + v1);
            acc += lgy;
        }
        if (lane < NA) s_csum[wid][lane] = acc;
    }
    __syncthreads();
    if (wid == 0 && lane < NA) {
        float run = -2.5649493574615367f;  // -log(13)
#pragma unroll
        for (int w = 0; w < 8; ++w) {
            s_carry[w][lane] = run;
            run += s_csum[w][lane];
        }
    }
    __syncthreads();

    // ---- phase 2: reduce over a per row ----
    for (int t = wid; t < TT; t += 8) {
        int cidx = (t * 1041) >> 16;  // t / 63 for t < 504
        float carry = s_carry[cidx][laneA];
        float v0 = -1e30f, v1 = -1e30f;
        if (lane < NA) {
            float2 v = gv[t * NA];
            v0 = v.x + carry;
            v1 = v.y + carry;
        }
        float M0 = v0, M1 = v1;
#pragma unroll
        for (int off = 8; off; off >>= 1) {
            M0 = fmaxf(M0, __shfl_xor_sync(0xffffffffu, M0, off));
            M1 = fmaxf(M1, __shfl_xor_sync(0xffffffffu, M1, off));
        }
        float e0 = __expf(v0 - M0), e1 = __expf(v1 - M1);
#pragma unroll
        for (int off = 8; off; off >>= 1) {
            e0 += __shfl_xor_sync(0xffffffffu, e0, off);
            e1 += __shfl_xor_sync(0xffffffffu, e1, off);
        }
        if (lane == 0) {
            float o0 = M0 + __logf(e0);
            float o1 = M1 + __logf(e1);
            float m = fmaxf(o0, o1);
            float zo = m + __logf(__expf(o0 - m) + __expf(o1 - m));
            ((float2*)out)[b * TT + t] = make_float2(o0 - zo, o1 - zo);
        }
    }
}

// ---------------------------------------------------------------------------
// inputs: 0 corr[i32 B,T] 1 kc 2 problem 3 FM[f32 B,T,200]
//         4 trans_logits[f32 100,2,2] 5 obs_logits_problem[f32 10000,2,2]
//         6 obs_logits_kc[f32 100,2,2] 7 init_logits[f32 100,2]
//         8 lr_w[f32 2,200] 9 lr_b[f32 2]     output: f32 [B,T,2]
// ---------------------------------------------------------------------------
extern "C" void kernel_launch(void* const* d_in, const int* in_sizes, int n_in,
                              void* d_out, int out_size) {
    const int*   corr = (const int*)d_in[0];
    const int*   kcp  = (const int*)d_in[1];
    const int*   prob = (const int*)d_in[2];
    const float* FM   = (const float*)d_in[3];
    const float* tl   = (const float*)d_in[4];
    const float* olp  = (const float*)d_in[5];
    const float* olk  = (const float*)d_in[6];
    const float* il   = (const float*)d_in[7];
    const float* lrw  = (const float*)d_in[8];
    const float* lrb  = (const float*)d_in[9];
    float* out = (float*)d_out;

    x_kernel<<<(BB * TT / 2 + 7) / 8, 256>>>(FM, lrw, lrb);
    scan_kernel<<<BB, 32>>>(corr, kcp, prob, tl, olp, olk, il);
    post_kernel<<<BB, 256>>>(corr, out);
}

// round 8
// speedup vs baseline: 1.3833x; 1.3833x over previous
#include <cuda_runtime.h>

#define BB 256
#define TT 500
#define NC 100
#define NA 13

// scratch: x = FM @ lr_w^T + lr_b  [B,T,2]
__device__ float g_x[BB * TT * 2];
// scratch: per-(b,t,a) chunk-local (prefix + lg_o) pairs
__device__ float2 g_v[BB * TT * NA];

// ---------------------------------------------------------------------------
// Kernel 1: x[b,t,o] = sum_f FM[b,t,f] * lr_w[o,f] + lr_b[o]
// ---------------------------------------------------------------------------
__global__ void __launch_bounds__(256) x_kernel(const float* __restrict__ FM,
                                                const float* __restrict__ lr_w,
                                                const float* __restrict__ lr_b) {
    __shared__ float4 w0[50], w1[50];
    int tid = threadIdx.x;
    if (tid < 50) {
        w0[tid] = ((const float4*)lr_w)[tid];
        w1[tid] = ((const float4*)lr_w)[50 + tid];
    }
    __syncthreads();
    int lane = tid & 31;
    int wrow = (blockIdx.x * 8 + (tid >> 5)) * 2;
    if (wrow >= BB * TT) return;
    const float4* fa = (const float4*)(FM + (size_t)wrow * 200);
    const float4* fb = fa + 50;

    float4 va0 = __ldg(fa + lane);
    float4 vb0 = __ldg(fb + lane);
    float4 va1, vb1;
    bool tail = lane < 18;
    if (tail) {
        va1 = __ldg(fa + 32 + lane);
        vb1 = __ldg(fb + 32 + lane);
    }
    float4 u = w0[lane], s = w1[lane];
    float a0 = va0.x * u.x + va0.y * u.y + va0.z * u.z + va0.w * u.w;
    float a1 = va0.x * s.x + va0.y * s.y + va0.z * s.z + va0.w * s.w;
    float b0 = vb0.x * u.x + vb0.y * u.y + vb0.z * u.z + vb0.w * u.w;
    float b1 = vb0.x * s.x + vb0.y * s.y + vb0.z * s.z + vb0.w * s.w;
    if (tail) {
        float4 u2 = w0[32 + lane], s2 = w1[32 + lane];
        a0 += va1.x * u2.x + va1.y * u2.y + va1.z * u2.z + va1.w * u2.w;
        a1 += va1.x * s2.x + va1.y * s2.y + va1.z * s2.z + va1.w * s2.w;
        b0 += vb1.x * u2.x + vb1.y * u2.y + vb1.z * u2.z + vb1.w * u2.w;
        b1 += vb1.x * s2.x + vb1.y * s2.y + vb1.z * s2.z + vb1.w * s2.w;
    }
#pragma unroll
    for (int off = 16; off; off >>= 1) {
        a0 += __shfl_xor_sync(0xffffffffu, a0, off);
        a1 += __shfl_xor_sync(0xffffffffu, a1, off);
        b0 += __shfl_xor_sync(0xffffffffu, b0, off);
        b1 += __shfl_xor_sync(0xffffffffu, b1, off);
    }
    if (lane == 0) {
        float bb0 = __ldg(lr_b), bb1 = __ldg(lr_b + 1);
        ((float4*)g_x)[wrow >> 1] = make_float4(a0 + bb0, a1 + bb1, b0 + bb0, b1 + bb1);
    }
}

// ---------------------------------------------------------------------------
// Kernel 2 (fused): per-batch block. Decomposes the T=500 serial scan into
// 100 independent per-chain sub-sequences (avg length 5): alpha lives in
// registers per (warp, chain); Gy -> smem. Then in-block postprocess:
// 8-way chunked log-prefix for ability + 13-lane lse reduction per row.
// ---------------------------------------------------------------------------
#define CH 63
__global__ void __launch_bounds__(256) bkt_kernel(
    const int* __restrict__ corr, const int* __restrict__ kc,
    const int* __restrict__ prob, const float* __restrict__ trans_logits,
    const float* __restrict__ olp, const float* __restrict__ olk,
    const float* __restrict__ init_logits, float* __restrict__ out) {
    __shared__ float  s_G[TT * NA];      // Gy per (t, a)          26000 B
    __shared__ float4 s_z[TT];           // (sy*D0, sy*D1, sy, 0)   8000 B
    __shared__ float4 s_T[NC];           // trans probs per chain   1600 B
    __shared__ float2 s_init[NC];        // init alpha               800 B
    __shared__ int    s_kc[TT];          //                         2000 B
    __shared__ int    s_ord[TT];         // t's sorted by chain     2000 B
    __shared__ int    s_start[NC + 1];   // chain offsets
    __shared__ int    s_cnt[NC];
    __shared__ int    s_pos[NC];
    __shared__ float  s_csum[8][NA];
    __shared__ float  s_carry[8][NA];

    const int b = blockIdx.x;
    const int tid = threadIdx.x;
    const int wid = tid >> 5;
    const int lane = tid & 31;
    const int laneA = (lane < NA) ? lane : 0;
    const float ab2 = 2.f * (-3.0f + 0.5f * (float)laneA);

    const float4* olp4 = (const float4*)olp;
    const float4* olk4 = (const float4*)olk;
    const float4* tl4  = (const float4*)trans_logits;
    const float2* gx2  = (const float2*)g_x;

    // ---- stage per-step z table + kc ----
    for (int i = tid; i < TT; i += 256) {
        int c = kc[b * TT + i];
        int p = prob[b * TT + i];
        int y = corr[b * TT + i];
        s_kc[i] = c;
        float4 op = __ldg(olp4 + p);
        float4 ok = __ldg(olk4 + c);
        float2 xv = gx2[b * TT + i];
        float sy = y ? 1.f : -1.f;
        float D0 = (op.y - op.x) + (ok.y - ok.x) - 2.f * xv.x;
        float D1 = (op.w - op.z) + (ok.w - ok.z) - 2.f * xv.y;
        s_z[i] = make_float4(sy * D0, sy * D1, sy, 0.f);
    }
    // ---- stage per-chain tables ----
    for (int i = tid; i < NC; i += 256) {
        float4 t = __ldg(tl4 + i);  // [sn0,so0],[sn0,so1]? layout: [sn][so] flat
        float m0 = fmaxf(t.x, t.z), m1 = fmaxf(t.y, t.w);
        float e00 = __expf(t.x - m0), e10 = __expf(t.z - m0);
        float e01 = __expf(t.y - m1), e11 = __expf(t.w - m1);
        float r0 = __fdividef(1.f, e00 + e10);
        float r1 = __fdividef(1.f, e01 + e11);
        s_T[i] = make_float4(e00 * r0, e01 * r1, e10 * r0, e11 * r1);
        float2 il = ((const float2*)init_logits)[i];
        float m = fmaxf(il.x, il.y);
        float ex = __expf(il.x - m), ey = __expf(il.y - m);
        float ri = __fdividef(1.f, ex + ey);
        s_init[i] = make_float2(ex * ri, ey * ri);
        s_cnt[i] = 0;
        s_pos[i] = 0;
    }
    __syncthreads();

    // ---- count occurrences per chain ----
    for (int i = tid; i < TT; i += 256) atomicAdd(&s_cnt[s_kc[i]], 1);
    __syncthreads();
    if (tid == 0) {
        int run = 0;
#pragma unroll 4
        for (int c = 0; c < NC; ++c) { s_start[c] = run; run += s_cnt[c]; }
        s_start[NC] = run;
    }
    __syncthreads();
    // ---- order-preserving fill (warp 0, match_any rank trick) ----
    if (wid == 0) {
        for (int base = 0; base < TT; base += 32) {
            int t = base + lane;
            bool valid = t < TT;
            unsigned am = __ballot_sync(0xffffffffu, valid);
            if (valid) {
                int c = s_kc[t];
                unsigned m = __match_any_sync(am, c);
                int rank = __popc(m & ((1u << lane) - 1u));
                int base0 = s_pos[c];
                s_ord[s_start[c] + base0 + rank] = t;
                int leader = 31 - __clz(m);
                if (lane == leader) s_pos[c] = base0 + __popc(m);
            }
            __syncwarp();
        }
    }
    __syncthreads();

    // ---- main: 8 warps sweep 100 chains; alpha in registers ----
    for (int c = wid; c < NC; c += 8) {
        int st = s_start[c], en = s_start[c + 1];
        if (st == en) continue;
        float2 Ai = s_init[c];
        float A0 = Ai.x, A1 = Ai.y;
        float4 T = s_T[c];
        for (int i = st; i < en; ++i) {
            int t = s_ord[i];
            float4 zz = s_z[t];
            float z0 = fmaf(zz.z, ab2, zz.x);
            float z1 = fmaf(zz.z, ab2, zz.y);
            float f0 = 1.f + __expf(-z0);   // 1/p0
            float f1 = 1.f + __expf(-z1);   // 1/p1
            float v0 = A0 * f1, v1 = A1 * f0;
            float sS = v0 + v1;
            float Gy = __fdividef(sS, f0 * f1);  // prob of observed outcome
            if (lane < NA) s_G[t * NA + lane] = Gy;
            float r = __fdividef(1.f, sS);       // renormalize: sum_snew = Gy
            A0 = fmaf(v0, T.x, v1 * T.y) * r;
            A1 = fmaf(v0, T.z, v1 * T.w) * r;
        }
    }
    __syncthreads();

    // ---- post phase 1: chunked prefix of log(Gy) ----
    if (lane < NA) {
        float2* gv = g_v + (size_t)b * TT * NA + lane;
        int t0 = wid * CH;
        int t1 = min(t0 + CH, TT);
        float acc = 0.f;
        for (int t = t0; t < t1; ++t) {
            float Gy = s_G[t * NA + lane];
            bool y = s_z[t].z > 0.f;
            float lgy = __logf(Gy);
            float lgo = __logf(fmaxf(1.f - Gy, 1e-37f));
            float v0 = y ? lgo : lgy;
            float v1 = y ? lgy : lgo;
            gv[t * NA] = make_float2(acc + v0, acc + v1);
            acc += lgy;
        }
        s_csum[wid][lane] = acc;
    }
    __syncthreads();
    if (wid == 0 && lane < NA) {
        float run = -2.5649493574615367f;  // -log(13)
#pragma unroll
        for (int w = 0; w < 8; ++w) {
            s_carry[w][lane] = run;
            run += s_csum[w][lane];
        }
    }
    __syncthreads();

    // ---- post phase 2: lse over a, normalize over o ----
    const float2* gvr = g_v + (size_t)b * TT * NA + laneA;
    for (int t = wid; t < TT; t += 8) {
        int cidx = (t * 1041) >> 16;  // t / 63 for t < 504
        float carry = s_carry[cidx][laneA];
        float v0 = -1e30f, v1 = -1e30f;
        if (lane < NA) {
            float2 v = gvr[t * NA];
            v0 = v.x + carry;
            v1 = v.y + carry;
        }
        float M0 = v0, M1 = v1;
#pragma unroll
        for (int off = 8; off; off >>= 1) {
            M0 = fmaxf(M0, __shfl_xor_sync(0xffffffffu, M0, off));
            M1 = fmaxf(M1, __shfl_xor_sync(0xffffffffu, M1, off));
        }
        float e0 = __expf(v0 - M0), e1 = __expf(v1 - M1);
#pragma unroll
        for (int off = 8; off; off >>= 1) {
            e0 += __shfl_xor_sync(0xffffffffu, e0, off);
            e1 += __shfl_xor_sync(0xffffffffu, e1, off);
        }
        if (lane == 0) {
            float o0 = M0 + __logf(e0);
            float o1 = M1 + __logf(e1);
            float m = fmaxf(o0, o1);
            float zo = m + __logf(__expf(o0 - m) + __expf(o1 - m));
            ((float2*)out)[b * TT + t] = make_float2(o0 - zo, o1 - zo);
        }
    }
}

// ---------------------------------------------------------------------------
// inputs: 0 corr[i32 B,T] 1 kc 2 problem 3 FM[f32 B,T,200]
//         4 trans_logits[f32 100,2,2] 5 obs_logits_problem[f32 10000,2,2]
//         6 obs_logits_kc[f32 100,2,2] 7 init_logits[f32 100,2]
//         8 lr_w[f32 2,200] 9 lr_b[f32 2]     output: f32 [B,T,2]
// ---------------------------------------------------------------------------
extern "C" void kernel_launch(void* const* d_in, const int* in_sizes, int n_in,
                              void* d_out, int out_size) {
    const int*   corr = (const int*)d_in[0];
    const int*   kcp  = (const int*)d_in[1];
    const int*   prob = (const int*)d_in[2];
    const float* FM   = (const float*)d_in[3];
    const float* tl   = (const float*)d_in[4];
    const float* olp  = (const float*)d_in[5];
    const float* olk  = (const float*)d_in[6];
    const float* il   = (const float*)d_in[7];
    const float* lrw  = (const float*)d_in[8];
    const float* lrb  = (const float*)d_in[9];
    float* out = (float*)d_out;

    x_kernel<<<(BB * TT / 2 + 7) / 8, 256>>>(FM, lrw, lrb);
    bkt_kernel<<<BB, 256>>>(corr, kcp, prob, tl, olp, olk, il, out);
}

// round 9
// speedup vs baseline: 1.7847x; 1.2902x over previous
#include <cuda_runtime.h>

#define BB 256
#define TT 500
#define NC 100
#define NA 13

// scratch: x = FM @ lr_w^T + lr_b  [B,T,2]
__device__ float g_x[BB * TT * 2];

// ---------------------------------------------------------------------------
// Kernel 1: x[b,t,o] = sum_f FM[b,t,f] * lr_w[o,f] + lr_b[o]
// Four rows per warp -> 8 independent LDG.128 in flight.
// ---------------------------------------------------------------------------
__global__ void __launch_bounds__(256) x_kernel(const float* __restrict__ FM,
                                                const float* __restrict__ lr_w,
                                                const float* __restrict__ lr_b) {
    __shared__ float4 w0[50], w1[50];
    int tid = threadIdx.x;
    if (tid < 50) {
        w0[tid] = ((const float4*)lr_w)[tid];
        w1[tid] = ((const float4*)lr_w)[50 + tid];
    }
    __syncthreads();
    int lane = tid & 31;
    int r = (blockIdx.x * 8 + (tid >> 5)) * 4;  // rows r..r+3
    if (r >= BB * TT) return;
    const float4* fp = (const float4*)(FM + (size_t)r * 200);
    bool tail = lane < 18;

    float4 A0 = __ldg(fp + lane);
    float4 A1 = __ldg(fp + 50 + lane);
    float4 A2 = __ldg(fp + 100 + lane);
    float4 A3 = __ldg(fp + 150 + lane);
    float4 B0, B1, B2, B3;
    if (tail) {
        B0 = __ldg(fp + 32 + lane);
        B1 = __ldg(fp + 82 + lane);
        B2 = __ldg(fp + 132 + lane);
        B3 = __ldg(fp + 182 + lane);
    }
    float4 u = w0[lane], s = w1[lane];
    float d00 = A0.x*u.x + A0.y*u.y + A0.z*u.z + A0.w*u.w;
    float d01 = A0.x*s.x + A0.y*s.y + A0.z*s.z + A0.w*s.w;
    float d10 = A1.x*u.x + A1.y*u.y + A1.z*u.z + A1.w*u.w;
    float d11 = A1.x*s.x + A1.y*s.y + A1.z*s.z + A1.w*s.w;
    float d20 = A2.x*u.x + A2.y*u.y + A2.z*u.z + A2.w*u.w;
    float d21 = A2.x*s.x + A2.y*s.y + A2.z*s.z + A2.w*s.w;
    float d30 = A3.x*u.x + A3.y*u.y + A3.z*u.z + A3.w*u.w;
    float d31 = A3.x*s.x + A3.y*s.y + A3.z*s.z + A3.w*s.w;
    if (tail) {
        float4 u2 = w0[32 + lane], s2 = w1[32 + lane];
        d00 += B0.x*u2.x + B0.y*u2.y + B0.z*u2.z + B0.w*u2.w;
        d01 += B0.x*s2.x + B0.y*s2.y + B0.z*s2.z + B0.w*s2.w;
        d10 += B1.x*u2.x + B1.y*u2.y + B1.z*u2.z + B1.w*u2.w;
        d11 += B1.x*s2.x + B1.y*s2.y + B1.z*s2.z + B1.w*s2.w;
        d20 += B2.x*u2.x + B2.y*u2.y + B2.z*u2.z + B2.w*u2.w;
        d21 += B2.x*s2.x + B2.y*s2.y + B2.z*s2.z + B2.w*s2.w;
        d30 += B3.x*u2.x + B3.y*u2.y + B3.z*u2.z + B3.w*u2.w;
        d31 += B3.x*s2.x + B3.y*s2.y + B3.z*s2.z + B3.w*s2.w;
    }
#pragma unroll
    for (int off = 16; off; off >>= 1) {
        d00 += __shfl_xor_sync(0xffffffffu, d00, off);
        d01 += __shfl_xor_sync(0xffffffffu, d01, off);
        d10 += __shfl_xor_sync(0xffffffffu, d10, off);
        d11 += __shfl_xor_sync(0xffffffffu, d11, off);
        d20 += __shfl_xor_sync(0xffffffffu, d20, off);
        d21 += __shfl_xor_sync(0xffffffffu, d21, off);
        d30 += __shfl_xor_sync(0xffffffffu, d30, off);
        d31 += __shfl_xor_sync(0xffffffffu, d31, off);
    }
    if (lane == 0) {
        float bb0 = __ldg(lr_b), bb1 = __ldg(lr_b + 1);
        ((float4*)g_x)[(r >> 1)]     = make_float4(d00 + bb0, d01 + bb1, d10 + bb0, d11 + bb1);
        ((float4*)g_x)[(r >> 1) + 1] = make_float4(d20 + bb0, d21 + bb1, d30 + bb0, d31 + bb1);
    }
}

// ---------------------------------------------------------------------------
// Kernel 2 (fused, all-smem): per-batch block.
//   1) stage z-table + per-chain T/init
//   2) parallel stable counting sort of timesteps by chain (8 warps)
//   3) balanced per-chain sweep (alpha in regs, prefetched), Gy -> smem
//   4) post: chunked log-prefix carries + half-warp-folded lse reduction
// ---------------------------------------------------------------------------
__global__ void __launch_bounds__(256) bkt_kernel(
    const int* __restrict__ corr, const int* __restrict__ kc,
    const int* __restrict__ prob, const float* __restrict__ trans_logits,
    const float* __restrict__ olp, const float* __restrict__ olk,
    const float* __restrict__ init_logits, float* __restrict__ out) {
    __shared__ float  s_G[TT * NA];      // Gy per (t, a)          26000 B
    __shared__ float4 s_z[TT];           // (sy*D0, sy*D1, sy, 0)   8000 B
    __shared__ float4 s_T[NC];           // trans probs             1600 B
    __shared__ float2 s_init[NC];        //                          800 B
    __shared__ int    s_kc[TT];          //                         2000 B
    __shared__ int    s_ord[TT];         //                         2000 B
    __shared__ int    s_start[NC + 4];   //                          416 B
    __shared__ int    s_cnt8[8][NC];     //                         3200 B
    __shared__ float  s_csum[8][NA];
    __shared__ float  s_carry[8][NA];

    const int b = blockIdx.x;
    const int tid = threadIdx.x;
    const int wid = tid >> 5;
    const int lane = tid & 31;
    const int laneA = (lane < NA) ? lane : 0;
    const float ab2 = 2.f * (-3.0f + 0.5f * (float)laneA);
    const int t0 = wid * 63;
    const int t1 = min(t0 + 63, TT);

    const float4* olp4 = (const float4*)olp;
    const float4* olk4 = (const float4*)olk;
    const float4* tl4  = (const float4*)trans_logits;
    const float2* gx2  = (const float2*)g_x;

    // ---- stage z table + kc; zero histograms ----
    for (int i = tid; i < TT; i += 256) {
        int c = kc[b * TT + i];
        int p = prob[b * TT + i];
        int y = corr[b * TT + i];
        s_kc[i] = c;
        float4 op = __ldg(olp4 + p);
        float4 ok = __ldg(olk4 + c);
        float2 xv = gx2[b * TT + i];
        float sy = y ? 1.f : -1.f;
        float D0 = (op.y - op.x) + (ok.y - ok.x) - 2.f * xv.x;
        float D1 = (op.w - op.z) + (ok.w - ok.z) - 2.f * xv.y;
        s_z[i] = make_float4(sy * D0, sy * D1, sy, 0.f);
    }
    for (int i = tid; i < 8 * NC; i += 256) (&s_cnt8[0][0])[i] = 0;
    for (int i = tid; i < NC; i += 256) {
        float4 t = __ldg(tl4 + i);
        float m0 = fmaxf(t.x, t.z), m1 = fmaxf(t.y, t.w);
        float e00 = __expf(t.x - m0), e10 = __expf(t.z - m0);
        float e01 = __expf(t.y - m1), e11 = __expf(t.w - m1);
        float r0 = __fdividef(1.f, e00 + e10);
        float r1 = __fdividef(1.f, e01 + e11);
        s_T[i] = make_float4(e00 * r0, e01 * r1, e10 * r0, e11 * r1);
        float2 il = ((const float2*)init_logits)[i];
        float m = fmaxf(il.x, il.y);
        float ex = __expf(il.x - m), ey = __expf(il.y - m);
        float ri = __fdividef(1.f, ex + ey);
        s_init[i] = make_float2(ex * ri, ey * ri);
    }
    __syncthreads();

    // ---- sort pass 1: per-segment histogram ----
    for (int t = t0 + lane; t < t1; t += 32) atomicAdd(&s_cnt8[wid][s_kc[t]], 1);
    __syncthreads();
    // ---- per-chain exclusive prefix over segments; chain totals ----
    if (tid < NC) {
        int run = 0;
#pragma unroll
        for (int w = 0; w < 8; ++w) {
            int v = s_cnt8[w][tid];
            s_cnt8[w][tid] = run;
            run += v;
        }
        s_start[tid] = run;  // total per chain (temp)
    }
    __syncthreads();
    // ---- exclusive scan over 100 chain totals (warp 0) ----
    if (wid == 0) {
        int base4 = lane * 4;
        int v0 = 0, v1 = 0, v2 = 0, v3 = 0;
        if (lane < 25) {
            v0 = s_start[base4]; v1 = s_start[base4 + 1];
            v2 = s_start[base4 + 2]; v3 = s_start[base4 + 3];
        }
        int sum = v0 + v1 + v2 + v3;
        int inc = sum;
#pragma unroll
        for (int off = 1; off < 32; off <<= 1) {
            int n = __shfl_up_sync(0xffffffffu, inc, off);
            if (lane >= off) inc += n;
        }
        int ex = inc - sum;
        if (lane < 25) {
            s_start[base4]     = ex;
            s_start[base4 + 1] = ex + v0;
            s_start[base4 + 2] = ex + v0 + v1;
            s_start[base4 + 3] = ex + v0 + v1 + v2;
        }
        if (lane == 24) s_start[NC] = ex + sum;  // == TT
    }
    __syncthreads();
    // ---- add chain bases into per-segment offsets ----
    if (tid < NC) {
        int st = s_start[tid];
#pragma unroll
        for (int w = 0; w < 8; ++w) s_cnt8[w][tid] += st;
    }
    __syncthreads();
    // ---- sort pass 2: fill (order-preserving; all 8 warps) ----
    for (int base = t0; base < t1; base += 32) {
        int t = base + lane;
        bool valid = t < t1;
        unsigned am = __ballot_sync(0xffffffffu, valid);
        if (valid) {
            int c = s_kc[t];
            unsigned m = __match_any_sync(am, c);
            int rank = __popc(m & ((1u << lane) - 1u));
            int b0 = s_cnt8[wid][c];
            s_ord[b0 + rank] = t;
            int leader = 31 - __clz(m);
            if (lane == leader) s_cnt8[wid][c] = b0 + __popc(m);
        }
        __syncwarp();
    }
    __syncthreads();

    // ---- balanced sweep: chain c -> warp s_start[c]/63; prefetched ----
    for (int c = 0; c < NC; ++c) {
        int st = s_start[c], en = s_start[c + 1];
        if (st == en) continue;
        if (((st * 1041) >> 16) != wid) continue;
        float2 Ai = s_init[c];
        float A0 = Ai.x, A1 = Ai.y;
        float4 T = s_T[c];
        int t = s_ord[st];
        float4 zz = s_z[t];
        for (int i = st; i < en; ++i) {
            int tn = (i + 1 < en) ? s_ord[i + 1] : 0;
            float4 zn = s_z[tn];
            float z0 = fmaf(zz.z, ab2, zz.x);
            float z1 = fmaf(zz.z, ab2, zz.y);
            float f0 = 1.f + __expf(-z0);    // 1/p0
            float f1 = 1.f + __expf(-z1);    // 1/p1
            float v0 = A0 * f1, v1 = A1 * f0;
            float sS = v0 + v1;
            float Gy = __fdividef(sS, f0 * f1);
            if (lane < NA) s_G[t * NA + lane] = Gy;
            float r = __fdividef(1.f, sS);
            A0 = fmaf(v0, T.x, v1 * T.y) * r;
            A1 = fmaf(v0, T.z, v1 * T.w) * r;
            t = tn; zz = zn;
        }
    }
    __syncthreads();

    // ---- post 1a: chunk sums of log(Gy) (2-way interleaved chains) ----
    {
        float a0 = 0.f, a1 = 0.f;
        int t = t0;
        for (; t + 1 < t1; t += 2) {
            a0 += __logf(s_G[t * NA + laneA]);
            a1 += __logf(s_G[(t + 1) * NA + laneA]);
        }
        if (t < t1) a0 += __logf(s_G[t * NA + laneA]);
        if (lane < NA) s_csum[wid][lane] = a0 + a1;
    }
    __syncthreads();
    if (wid == 0 && lane < NA) {
        float run = -2.5649493574615367f;  // -log(13)
#pragma unroll
        for (int w = 0; w < 8; ++w) {
            s_carry[w][lane] = run;
            run += s_csum[w][lane];
        }
    }
    __syncthreads();

    // ---- post 1b: serial chunk pass; half-warp-folded lse over a ----
    {
        float acc = s_carry[wid][laneA];
        for (int t = t0; t < t1; ++t) {
            float Gy = s_G[t * NA + laneA];
            bool y = s_z[t].z > 0.f;
            float lgy = __logf(Gy);
            float lgo = __logf(fmaxf(1.f - Gy, 1e-37f));
            float w0v = acc + (y ? lgo : lgy);
            float w1v = acc + (y ? lgy : lgo);
            acc += lgy;
            // fold o=1 into lanes 16-31
            float w1x = __shfl_sync(0xffffffffu, w1v, lane & 15);
            float zv = (lane < 16) ? w0v : w1x;
            if ((lane & 15) >= NA) zv = -1e30f;
            float M = zv;
#pragma unroll
            for (int off = 8; off; off >>= 1)
                M = fmaxf(M, __shfl_xor_sync(0xffffffffu, M, off));
            float e = __expf(zv - M);
#pragma unroll
            for (int off = 8; off; off >>= 1)
                e += __shfl_xor_sync(0xffffffffu, e, off);
            float Mo = __shfl_sync(0xffffffffu, M, 16);
            float eo = __shfl_sync(0xffffffffu, e, 16);
            if (lane == 0) {
                float o0 = M + __logf(e);
                float o1 = Mo + __logf(eo);
                float m = fmaxf(o0, o1);
                float zo = m + __logf(__expf(o0 - m) + __expf(o1 - m));
                ((float2*)out)[b * TT + t] = make_float2(o0 - zo, o1 - zo);
            }
        }
    }
}

// ---------------------------------------------------------------------------
// inputs: 0 corr[i32 B,T] 1 kc 2 problem 3 FM[f32 B,T,200]
//         4 trans_logits[f32 100,2,2] 5 obs_logits_problem[f32 10000,2,2]
//         6 obs_logits_kc[f32 100,2,2] 7 init_logits[f32 100,2]
//         8 lr_w[f32 2,200] 9 lr_b[f32 2]     output: f32 [B,T,2]
// ---------------------------------------------------------------------------
extern "C" void kernel_launch(void* const* d_in, const int* in_sizes, int n_in,
                              void* d_out, int out_size) {
    const int*   corr = (const int*)d_in[0];
    const int*   kcp  = (const int*)d_in[1];
    const int*   prob = (const int*)d_in[2];
    const float* FM   = (const float*)d_in[3];
    const float* tl   = (const float*)d_in[4];
    const float* olp  = (const float*)d_in[5];
    const float* olk  = (const float*)d_in[6];
    const float* il   = (const float*)d_in[7];
    const float* lrw  = (const float*)d_in[8];
    const float* lrb  = (const float*)d_in[9];
    float* out = (float*)d_out;

    x_kernel<<<(BB * TT / 4 + 7) / 8, 256>>>(FM, lrw, lrb);
    bkt_kernel<<<BB, 256>>>(corr, kcp, prob, tl, olp, olk, il, out);
}

// round 10
// speedup vs baseline: 2.6241x; 1.4704x over previous
#include <cuda_runtime.h>

#define BB 256
#define TT 500
#define NC 100
#define NA 13

// scratch: x = FM @ lr_w^T + lr_b  [B,T,2]
__device__ float g_x[BB * TT * 2];

// ---------------------------------------------------------------------------
// Kernel 1: x[b,t,o] = sum_f FM[b,t,f] * lr_w[o,f] + lr_b[o]
// Four rows per warp -> 8 independent LDG.128 in flight.
// ---------------------------------------------------------------------------
__global__ void __launch_bounds__(256) x_kernel(const float* __restrict__ FM,
                                                const float* __restrict__ lr_w,
                                                const float* __restrict__ lr_b) {
    __shared__ float4 w0[50], w1[50];
    int tid = threadIdx.x;
    if (tid < 50) {
        w0[tid] = ((const float4*)lr_w)[tid];
        w1[tid] = ((const float4*)lr_w)[50 + tid];
    }
    __syncthreads();
    int lane = tid & 31;
    int r = (blockIdx.x * 8 + (tid >> 5)) * 4;  // rows r..r+3
    if (r >= BB * TT) return;
    const float4* fp = (const float4*)(FM + (size_t)r * 200);
    bool tail = lane < 18;

    float4 A0 = __ldg(fp + lane);
    float4 A1 = __ldg(fp + 50 + lane);
    float4 A2 = __ldg(fp + 100 + lane);
    float4 A3 = __ldg(fp + 150 + lane);
    float4 B0, B1, B2, B3;
    if (tail) {
        B0 = __ldg(fp + 32 + lane);
        B1 = __ldg(fp + 82 + lane);
        B2 = __ldg(fp + 132 + lane);
        B3 = __ldg(fp + 182 + lane);
    }
    float4 u = w0[lane], s = w1[lane];
    float d00 = A0.x*u.x + A0.y*u.y + A0.z*u.z + A0.w*u.w;
    float d01 = A0.x*s.x + A0.y*s.y + A0.z*s.z + A0.w*s.w;
    float d10 = A1.x*u.x + A1.y*u.y + A1.z*u.z + A1.w*u.w;
    float d11 = A1.x*s.x + A1.y*s.y + A1.z*s.z + A1.w*s.w;
    float d20 = A2.x*u.x + A2.y*u.y + A2.z*u.z + A2.w*u.w;
    float d21 = A2.x*s.x + A2.y*s.y + A2.z*s.z + A2.w*s.w;
    float d30 = A3.x*u.x + A3.y*u.y + A3.z*u.z + A3.w*u.w;
    float d31 = A3.x*s.x + A3.y*s.y + A3.z*s.z + A3.w*s.w;
    if (tail) {
        float4 u2 = w0[32 + lane], s2 = w1[32 + lane];
        d00 += B0.x*u2.x + B0.y*u2.y + B0.z*u2.z + B0.w*u2.w;
        d01 += B0.x*s2.x + B0.y*s2.y + B0.z*s2.z + B0.w*s2.w;
        d10 += B1.x*u2.x + B1.y*u2.y + B1.z*u2.z + B1.w*u2.w;
        d11 += B1.x*s2.x + B1.y*s2.y + B1.z*s2.z + B1.w*s2.w;
        d20 += B2.x*u2.x + B2.y*u2.y + B2.z*u2.z + B2.w*u2.w;
        d21 += B2.x*s2.x + B2.y*s2.y + B2.z*s2.z + B2.w*s2.w;
        d30 += B3.x*u2.x + B3.y*u2.y + B3.z*u2.z + B3.w*u2.w;
        d31 += B3.x*s2.x + B3.y*s2.y + B3.z*s2.z + B3.w*s2.w;
    }
#pragma unroll
    for (int off = 16; off; off >>= 1) {
        d00 += __shfl_xor_sync(0xffffffffu, d00, off);
        d01 += __shfl_xor_sync(0xffffffffu, d01, off);
        d10 += __shfl_xor_sync(0xffffffffu, d10, off);
        d11 += __shfl_xor_sync(0xffffffffu, d11, off);
        d20 += __shfl_xor_sync(0xffffffffu, d20, off);
        d21 += __shfl_xor_sync(0xffffffffu, d21, off);
        d30 += __shfl_xor_sync(0xffffffffu, d30, off);
        d31 += __shfl_xor_sync(0xffffffffu, d31, off);
    }
    if (lane == 0) {
        float bb0 = __ldg(lr_b), bb1 = __ldg(lr_b + 1);
        ((float4*)g_x)[(r >> 1)]     = make_float4(d00 + bb0, d01 + bb1, d10 + bb0, d11 + bb1);
        ((float4*)g_x)[(r >> 1) + 1] = make_float4(d20 + bb0, d21 + bb1, d30 + bb0, d31 + bb1);
    }
}

// ---------------------------------------------------------------------------
// Kernel 2 (fused): per-batch block.
//   1) stage z-table + per-chain T/init
//   2) parallel stable counting sort of timesteps by chain (8 warps)
//   3) balanced per-chain sweep (alpha in regs, prefetched), Gy -> smem
//   4) post 1a: per-chunk log-prefix of Gy materialized to s_abil
//   5) post 2: THREAD-per-row linear-space lse (no shuffles, 3 logf/row)
// dynamic smem: s_G[TT*NA] + s_abil[TT*NA] = 52000 B
// ---------------------------------------------------------------------------
__global__ void __launch_bounds__(256) bkt_kernel(
    const int* __restrict__ corr, const int* __restrict__ kc,
    const int* __restrict__ prob, const float* __restrict__ trans_logits,
    const float* __restrict__ olp, const float* __restrict__ olk,
    const float* __restrict__ init_logits, float* __restrict__ out) {
    extern __shared__ float dsm[];
    float* s_G    = dsm;            // Gy per (t, a)            26000 B
    float* s_abil = dsm + TT * NA;  // chunk-local prefix       26000 B

    __shared__ float4 s_z[TT];           // (sy*D0, sy*D1, sy, 0)   8000 B
    __shared__ float4 s_T[NC];           // trans probs             1600 B
    __shared__ float2 s_init[NC];        //                          800 B
    __shared__ int    s_kc[TT];          //                         2000 B
    __shared__ int    s_ord[TT];         //                         2000 B
    __shared__ int    s_start[NC + 4];   //                          416 B
    __shared__ int    s_cnt8[8][NC];     //                         3200 B
    __shared__ float  s_csum[8][NA];
    __shared__ float  s_carry[8][NA];

    const int b = blockIdx.x;
    const int tid = threadIdx.x;
    const int wid = tid >> 5;
    const int lane = tid & 31;
    const int laneA = (lane < NA) ? lane : 0;
    const float ab2 = 2.f * (-3.0f + 0.5f * (float)laneA);
    const int t0 = wid * 63;
    const int t1 = min(t0 + 63, TT);

    const float4* olp4 = (const float4*)olp;
    const float4* olk4 = (const float4*)olk;
    const float4* tl4  = (const float4*)trans_logits;
    const float2* gx2  = (const float2*)g_x;

    // ---- stage z table + kc; zero histograms ----
    for (int i = tid; i < TT; i += 256) {
        int c = kc[b * TT + i];
        int p = prob[b * TT + i];
        int y = corr[b * TT + i];
        s_kc[i] = c;
        float4 op = __ldg(olp4 + p);
        float4 ok = __ldg(olk4 + c);
        float2 xv = gx2[b * TT + i];
        float sy = y ? 1.f : -1.f;
        float D0 = (op.y - op.x) + (ok.y - ok.x) - 2.f * xv.x;
        float D1 = (op.w - op.z) + (ok.w - ok.z) - 2.f * xv.y;
        s_z[i] = make_float4(sy * D0, sy * D1, sy, 0.f);
    }
    for (int i = tid; i < 8 * NC; i += 256) (&s_cnt8[0][0])[i] = 0;
    for (int i = tid; i < NC; i += 256) {
        float4 t = __ldg(tl4 + i);
        float m0 = fmaxf(t.x, t.z), m1 = fmaxf(t.y, t.w);
        float e00 = __expf(t.x - m0), e10 = __expf(t.z - m0);
        float e01 = __expf(t.y - m1), e11 = __expf(t.w - m1);
        float r0 = __fdividef(1.f, e00 + e10);
        float r1 = __fdividef(1.f, e01 + e11);
        s_T[i] = make_float4(e00 * r0, e01 * r1, e10 * r0, e11 * r1);
        float2 il = ((const float2*)init_logits)[i];
        float m = fmaxf(il.x, il.y);
        float ex = __expf(il.x - m), ey = __expf(il.y - m);
        float ri = __fdividef(1.f, ex + ey);
        s_init[i] = make_float2(ex * ri, ey * ri);
    }
    __syncthreads();

    // ---- sort pass 1: per-segment histogram ----
    for (int t = t0 + lane; t < t1; t += 32) atomicAdd(&s_cnt8[wid][s_kc[t]], 1);
    __syncthreads();
    // ---- per-chain exclusive prefix over segments; chain totals ----
    if (tid < NC) {
        int run = 0;
#pragma unroll
        for (int w = 0; w < 8; ++w) {
            int v = s_cnt8[w][tid];
            s_cnt8[w][tid] = run;
            run += v;
        }
        s_start[tid] = run;  // total per chain (temp)
    }
    __syncthreads();
    // ---- exclusive scan over 100 chain totals (warp 0) ----
    if (wid == 0) {
        int base4 = lane * 4;
        int v0 = 0, v1 = 0, v2 = 0, v3 = 0;
        if (lane < 25) {
            v0 = s_start[base4]; v1 = s_start[base4 + 1];
            v2 = s_start[base4 + 2]; v3 = s_start[base4 + 3];
        }
        int sum = v0 + v1 + v2 + v3;
        int inc = sum;
#pragma unroll
        for (int off = 1; off < 32; off <<= 1) {
            int n = __shfl_up_sync(0xffffffffu, inc, off);
            if (lane >= off) inc += n;
        }
        int ex = inc - sum;
        if (lane < 25) {
            s_start[base4]     = ex;
            s_start[base4 + 1] = ex + v0;
            s_start[base4 + 2] = ex + v0 + v1;
            s_start[base4 + 3] = ex + v0 + v1 + v2;
        }
        if (lane == 24) s_start[NC] = ex + sum;  // == TT
    }
    __syncthreads();
    // ---- add chain bases into per-segment offsets ----
    if (tid < NC) {
        int st = s_start[tid];
#pragma unroll
        for (int w = 0; w < 8; ++w) s_cnt8[w][tid] += st;
    }
    __syncthreads();
    // ---- sort pass 2: fill (order-preserving; all 8 warps) ----
    for (int base = t0; base < t1; base += 32) {
        int t = base + lane;
        bool valid = t < t1;
        unsigned am = __ballot_sync(0xffffffffu, valid);
        if (valid) {
            int c = s_kc[t];
            unsigned m = __match_any_sync(am, c);
            int rank = __popc(m & ((1u << lane) - 1u));
            int b0 = s_cnt8[wid][c];
            s_ord[b0 + rank] = t;
            int leader = 31 - __clz(m);
            if (lane == leader) s_cnt8[wid][c] = b0 + __popc(m);
        }
        __syncwarp();
    }
    __syncthreads();

    // ---- balanced sweep: chain c -> warp s_start[c]/63; prefetched ----
    for (int c = 0; c < NC; ++c) {
        int st = s_start[c], en = s_start[c + 1];
        if (st == en) continue;
        if (((st * 1041) >> 16) != wid) continue;
        float2 Ai = s_init[c];
        float A0 = Ai.x, A1 = Ai.y;
        float4 T = s_T[c];
        int t = s_ord[st];
        float4 zz = s_z[t];
        for (int i = st; i < en; ++i) {
            int tn = (i + 1 < en) ? s_ord[i + 1] : 0;
            float4 zn = s_z[tn];
            float z0 = fmaf(zz.z, ab2, zz.x);
            float z1 = fmaf(zz.z, ab2, zz.y);
            float f0 = 1.f + __expf(-z0);    // 1/p0
            float f1 = 1.f + __expf(-z1);    // 1/p1
            float v0 = A0 * f1, v1 = A1 * f0;
            float sS = v0 + v1;
            float Gy = __fdividef(sS, f0 * f1);
            if (lane < NA) s_G[t * NA + lane] = Gy;
            float r = __fdividef(1.f, sS);
            A0 = fmaf(v0, T.x, v1 * T.y) * r;
            A1 = fmaf(v0, T.z, v1 * T.w) * r;
            t = tn; zz = zn;
        }
    }
    __syncthreads();

    // ---- post 1a: chunk-local prefix of log(Gy), materialized ----
    if (lane < NA) {
        float acc = 0.f;
        for (int t = t0; t < t1; ++t) {
            float lgy = __logf(s_G[t * NA + lane]);
            s_abil[t * NA + lane] = acc;  // prefix BEFORE including step t
            acc += lgy;
        }
        s_csum[wid][lane] = acc;
    }
    __syncthreads();
    if (wid == 0 && lane < NA) {
        float run = -2.5649493574615367f;  // -log(13)
#pragma unroll
        for (int w = 0; w < 8; ++w) {
            s_carry[w][lane] = run;
            run += s_csum[w][lane];
        }
    }
    __syncthreads();

    // ---- post 2: thread-per-row, linear space ----
#pragma unroll
    for (int rr = 0; rr < 2; ++rr) {
        int t = tid + rr * 256;
        if (t >= TT) break;
        int ch = (t * 1041) >> 16;  // t / 63 for t < 504
        float ab[NA], G[NA];
        float M = -1e30f;
#pragma unroll
        for (int a = 0; a < NA; ++a) {
            G[a]  = s_G[t * NA + a];
            ab[a] = s_abil[t * NA + a] + s_carry[ch][a];
            M = fmaxf(M, ab[a]);
        }
        float Sy = 0.f, So = 0.f;
#pragma unroll
        for (int a = 0; a < NA; ++a) {
            float E = __expf(ab[a] - M);
            Sy = fmaf(E, G[a], Sy);
            So = fmaf(E, 1.f - G[a], So);
        }
        bool y = s_z[t].z > 0.f;
        float ly = __logf(Sy), lo = __logf(So), ls = __logf(Sy + So);
        float o0 = (y ? lo : ly) - ls;
        float o1 = (y ? ly : lo) - ls;
        ((float2*)out)[b * TT + t] = make_float2(o0, o1);
    }
}

// ---------------------------------------------------------------------------
// inputs: 0 corr[i32 B,T] 1 kc 2 problem 3 FM[f32 B,T,200]
//         4 trans_logits[f32 100,2,2] 5 obs_logits_problem[f32 10000,2,2]
//         6 obs_logits_kc[f32 100,2,2] 7 init_logits[f32 100,2]
//         8 lr_w[f32 2,200] 9 lr_b[f32 2]     output: f32 [B,T,2]
// ---------------------------------------------------------------------------
extern "C" void kernel_launch(void* const* d_in, const int* in_sizes, int n_in,
                              void* d_out, int out_size) {
    const int*   corr = (const int*)d_in[0];
    const int*   kcp  = (const int*)d_in[1];
    const int*   prob = (const int*)d_in[2];
    const float* FM   = (const float*)d_in[3];
    const float* tl   = (const float*)d_in[4];
    const float* olp  = (const float*)d_in[5];
    const float* olk  = (const float*)d_in[6];
    const float* il   = (const float*)d_in[7];
    const float* lrw  = (const float*)d_in[8];
    const float* lrb  = (const float*)d_in[9];
    float* out = (float*)d_out;

    const int DSMEM = TT * NA * 2 * (int)sizeof(float);  // 52000 B
    cudaFuncSetAttribute(bkt_kernel, cudaFuncAttributeMaxDynamicSharedMemorySize, DSMEM);

    x_kernel<<<(BB * TT / 4 + 7) / 8, 256>>>(FM, lrw, lrb);
    bkt_kernel<<<BB, 256, DSMEM>>>(corr, kcp, prob, tl, olp, olk, il, out);
}